// round 9
// baseline (speedup 1.0000x reference)
#include <cuda_runtime.h>
#include <math.h>

// ChannelAttention — R9: single kernel, persistent MLP "server" CTAs.
//   blockIdx 0..7        : server CTA for group o (stages w1[o],w2[o] in smem
//                          ONCE, spin-waits on per-blk counters, runs MLP).
//   blockIdx 8..16391    : pool CTAs — 8 warps x 1 channel-row, per-warp
//                          fence+atomic arrival, zero barriers, exit.
// x  : [B=8, O=8, S=32, C=64, 32, 32] fp32 (512 MB streamed once)
// w1 : [8,64,64], w2 : [8,64,64] fp32
// out: [B,O,S,C] fp32

#define C_DIM   64
#define HW_DIM  1024
#define O_DIM   8
#define S_DIM   32
#define NBLK    2048            // B*O*S
#define WPAD4   17              // padded row: 17 float4 = 272 B (conflict-free)
#define NSRV    8

__device__ float2       g_pool[NBLK * C_DIM];
__device__ unsigned int g_cnt[NBLK];      // zero-init; server resets -> replay-safe

__global__ __launch_bounds__(256, 6)
void fused_kernel(const float* __restrict__ x,
                  const float* __restrict__ w1,
                  const float* __restrict__ w2,
                  float* __restrict__ out)
{
    __shared__ float4 w1s4[C_DIM * WPAD4];     // 17408 B
    __shared__ float4 w2s4[C_DIM * WPAD4];     // 17408 B
    __shared__ __align__(16) float spm[4][C_DIM];
    __shared__ __align__(16) float spx[4][C_DIM];
    __shared__ __align__(16) float shs[4][C_DIM];

    const int tid  = threadIdx.x;
    const int lane = tid & 31;

    if (blockIdx.x >= NSRV) {
        // ================= pool CTA =================
        const int bx  = blockIdx.x - NSRV;
        const int wid = tid >> 5;
        const int gw  = bx * 8 + wid;          // row id = blk*64 + c
        const int blk = bx >> 3;

        const float4* row = reinterpret_cast<const float4*>(x)
                          + (size_t)gw * (HW_DIM / 4) + lane;

        float4 v0 = __ldcs(row + 0 * 32);
        float4 v1 = __ldcs(row + 1 * 32);
        float4 v2 = __ldcs(row + 2 * 32);
        float4 v3 = __ldcs(row + 3 * 32);
        float4 v4 = __ldcs(row + 4 * 32);
        float4 v5 = __ldcs(row + 5 * 32);
        float4 v6 = __ldcs(row + 6 * 32);
        float4 v7 = __ldcs(row + 7 * 32);

        float sa = (v0.x + v0.y) + (v0.z + v0.w);
        float sb = (v1.x + v1.y) + (v1.z + v1.w);
        float sc = (v2.x + v2.y) + (v2.z + v2.w);
        float sd = (v3.x + v3.y) + (v3.z + v3.w);
        sa += (v4.x + v4.y) + (v4.z + v4.w);
        sb += (v5.x + v5.y) + (v5.z + v5.w);
        sc += (v6.x + v6.y) + (v6.z + v6.w);
        sd += (v7.x + v7.y) + (v7.z + v7.w);

        float ma = fmaxf(fmaxf(v0.x, v0.y), fmaxf(v0.z, v0.w));
        float mb = fmaxf(fmaxf(v1.x, v1.y), fmaxf(v1.z, v1.w));
        float mc = fmaxf(fmaxf(v2.x, v2.y), fmaxf(v2.z, v2.w));
        float md = fmaxf(fmaxf(v3.x, v3.y), fmaxf(v3.z, v3.w));
        ma = fmaxf(ma, fmaxf(fmaxf(v4.x, v4.y), fmaxf(v4.z, v4.w)));
        mb = fmaxf(mb, fmaxf(fmaxf(v5.x, v5.y), fmaxf(v5.z, v5.w)));
        mc = fmaxf(mc, fmaxf(fmaxf(v6.x, v6.y), fmaxf(v6.z, v6.w)));
        md = fmaxf(md, fmaxf(fmaxf(v7.x, v7.y), fmaxf(v7.z, v7.w)));

        float s = (sa + sb) + (sc + sd);
        float m = fmaxf(fmaxf(ma, mb), fmaxf(mc, md));

        #pragma unroll
        for (int off = 16; off > 0; off >>= 1) {
            s += __shfl_xor_sync(0xFFFFFFFFu, s, off);
            m = fmaxf(m, __shfl_xor_sync(0xFFFFFFFFu, m, off));
        }
        if (lane == 0) {
            g_pool[gw] = make_float2(s * (1.0f / (float)HW_DIM), m);
            __threadfence();                     // release pooled write
            atomicAdd(&g_cnt[blk], 1u);          // 64 warp-arrivals per blk
        }
        return;
    }

    // ================= server CTA (one per group o) =================
    const int o = blockIdx.x;

    // stage weights ONCE (coalesced float4 -> padded smem rows)
    const float4* w1g4 = reinterpret_cast<const float4*>(w1 + (size_t)o * C_DIM * C_DIM);
    const float4* w2g4 = reinterpret_cast<const float4*>(w2 + (size_t)o * C_DIM * C_DIM);
    #pragma unroll
    for (int i = 0; i < 4; ++i) {
        int idx = tid + i * 256;                // 0..1023 float4s
        int r = idx >> 4, c4 = idx & 15;
        w1s4[r * WPAD4 + c4] = __ldg(w1g4 + idx);
        w2s4[r * WPAD4 + c4] = __ldg(w2g4 + idx);
    }
    __syncthreads();

    const int sub = tid >> 6;                   // 4 blks per iteration
    const int n   = tid & 63;

    for (int it = 0; it < 64; ++it) {
        // threads 0..3 spin on the 4 counters for this group of blks
        if (tid < 4) {
            int idx = it * 4 + tid;
            int blk = (idx >> 5) * 256 + o * S_DIM + (idx & 31);
            while (*(volatile unsigned int*)&g_cnt[blk] < 64u)
                __nanosleep(64);
            g_cnt[blk] = 0u;                    // reset for next graph replay
        }
        __syncthreads();                        // counters done => pooled data in L2

        const int idx = it * 4 + sub;
        const int blk = (idx >> 5) * 256 + o * S_DIM + (idx & 31);

        float2 p = __ldcg(&g_pool[blk * C_DIM + n]);   // bypass L1
        spm[sub][n] = p.x;
        spx[sub][n] = p.y;
        __syncthreads();

        // FC1 + relu
        {
            const float4* wr = w1s4 + n * WPAD4;
            const float4* p4 = reinterpret_cast<const float4*>(spm[sub]);
            const float4* q4 = reinterpret_cast<const float4*>(spx[sub]);
            float am = 0.0f, ax = 0.0f;
            #pragma unroll
            for (int c4 = 0; c4 < 16; ++c4) {
                float4 w = wr[c4];
                float4 pp = p4[c4];
                float4 qq = q4[c4];
                am = fmaf(w.x, pp.x, am); am = fmaf(w.y, pp.y, am);
                am = fmaf(w.z, pp.z, am); am = fmaf(w.w, pp.w, am);
                ax = fmaf(w.x, qq.x, ax); ax = fmaf(w.y, qq.y, ax);
                ax = fmaf(w.z, qq.z, ax); ax = fmaf(w.w, qq.w, ax);
            }
            shs[sub][n] = fmaxf(am, 0.0f) + fmaxf(ax, 0.0f);
        }
        __syncthreads();

        // FC2 + sigmoid (FC2 linear => single pass over summed hidden)
        {
            const float4* wr = w2s4 + n * WPAD4;
            const float4* h4 = reinterpret_cast<const float4*>(shs[sub]);
            float a = 0.0f;
            #pragma unroll
            for (int c4 = 0; c4 < 16; ++c4) {
                float4 w = wr[c4];
                float4 h = h4[c4];
                a = fmaf(w.x, h.x, a); a = fmaf(w.y, h.y, a);
                a = fmaf(w.z, h.z, a); a = fmaf(w.w, h.w, a);
            }
            out[(size_t)blk * C_DIM + n] = 1.0f / (1.0f + __expf(-a));
        }
        // next-iteration spm write is ordered by the counter __syncthreads above
    }
}

extern "C" void kernel_launch(void* const* d_in, const int* in_sizes, int n_in,
                              void* d_out, int out_size)
{
    const float* x  = (const float*)d_in[0];
    const float* w1 = (const float*)d_in[1];
    const float* w2 = (const float*)d_in[2];
    float* out = (float*)d_out;

    fused_kernel<<<NBLK * 8 + NSRV, 256>>>(x, w1, w2, out);
}

// round 10
// speedup vs baseline: 2.0368x; 2.0368x over previous
#include <cuda_runtime.h>
#include <math.h>

// ChannelAttention — R10: fused last-CTA kernel, tail amortized over 4 blks.
// x  : [B=8, O=8, S=32, C=64, 32, 32] fp32 (512 MB streamed once)
// w1 : [8,64,64], w2 : [8,64,64] fp32
// out: [B,O,S,C] fp32
//
// Grid = 16384 CTAs x 256 threads (8 warps = 8 channel rows; 8 CTAs per blk).
// Election group = 4 consecutive blks (same o) = 32 CTAs. Last-arriving CTA
// stages w1/w2 once and runs the MLP for all 4 blks (256 threads fully used).

#define C_DIM   64
#define HW_DIM  1024
#define O_DIM   8
#define S_DIM   32
#define NBLK    2048            // B*O*S
#define NGRP    512             // NBLK / 4
#define WPAD4   17              // padded weight row: 17 float4 (conflict-free)

__device__ float2       g_pool[NBLK * C_DIM];
__device__ unsigned int g_cnt[NGRP];      // zero-init; tail resets -> replay-safe

__global__ __launch_bounds__(256, 6)
void fused_kernel(const float* __restrict__ x,
                  const float* __restrict__ w1,
                  const float* __restrict__ w2,
                  float* __restrict__ out)
{
    __shared__ float4 ws4[C_DIM * WPAD4];      // staged w1, then reused for w2
    __shared__ __align__(16) float spm[4][C_DIM];
    __shared__ __align__(16) float spx[4][C_DIM];
    __shared__ __align__(16) float shs[4][C_DIM];
    __shared__ int sLast;

    const int tid  = threadIdx.x;
    const int lane = tid & 31;
    const int wid  = tid >> 5;                 // 8 warps
    const int gw   = blockIdx.x * 8 + wid;     // row id = blk*64 + c
    const int grp  = blockIdx.x >> 5;          // 32 CTAs per 4-blk group

    // ---------------- pooling: one warp per channel row ----------------
    const float4* row = reinterpret_cast<const float4*>(x) + (size_t)gw * (HW_DIM / 4) + lane;

    float4 v0 = __ldcs(row + 0 * 32);
    float4 v1 = __ldcs(row + 1 * 32);
    float4 v2 = __ldcs(row + 2 * 32);
    float4 v3 = __ldcs(row + 3 * 32);
    float4 v4 = __ldcs(row + 4 * 32);
    float4 v5 = __ldcs(row + 5 * 32);
    float4 v6 = __ldcs(row + 6 * 32);
    float4 v7 = __ldcs(row + 7 * 32);

    float sa = (v0.x + v0.y) + (v0.z + v0.w);
    float sb = (v1.x + v1.y) + (v1.z + v1.w);
    float sc = (v2.x + v2.y) + (v2.z + v2.w);
    float sd = (v3.x + v3.y) + (v3.z + v3.w);
    sa += (v4.x + v4.y) + (v4.z + v4.w);
    sb += (v5.x + v5.y) + (v5.z + v5.w);
    sc += (v6.x + v6.y) + (v6.z + v6.w);
    sd += (v7.x + v7.y) + (v7.z + v7.w);

    float ma = fmaxf(fmaxf(v0.x, v0.y), fmaxf(v0.z, v0.w));
    float mb = fmaxf(fmaxf(v1.x, v1.y), fmaxf(v1.z, v1.w));
    float mc = fmaxf(fmaxf(v2.x, v2.y), fmaxf(v2.z, v2.w));
    float md = fmaxf(fmaxf(v3.x, v3.y), fmaxf(v3.z, v3.w));
    ma = fmaxf(ma, fmaxf(fmaxf(v4.x, v4.y), fmaxf(v4.z, v4.w)));
    mb = fmaxf(mb, fmaxf(fmaxf(v5.x, v5.y), fmaxf(v5.z, v5.w)));
    mc = fmaxf(mc, fmaxf(fmaxf(v6.x, v6.y), fmaxf(v6.z, v6.w)));
    md = fmaxf(md, fmaxf(fmaxf(v7.x, v7.y), fmaxf(v7.z, v7.w)));

    float s = (sa + sb) + (sc + sd);
    float m = fmaxf(fmaxf(ma, mb), fmaxf(mc, md));

    #pragma unroll
    for (int off = 16; off > 0; off >>= 1) {
        s += __shfl_xor_sync(0xFFFFFFFFu, s, off);
        m = fmaxf(m, __shfl_xor_sync(0xFFFFFFFFu, m, off));
    }
    if (lane == 0)
        g_pool[gw] = make_float2(s * (1.0f / (float)HW_DIM), m);
    __syncthreads();                            // all warps' pooled writes issued

    // ---------------- last-CTA election (per 4-blk group) ----------------
    if (tid == 0) {
        __threadfence();                        // release this CTA's pooled writes
        unsigned int old = atomicAdd(&g_cnt[grp], 1u);
        if (old == 31u) { sLast = 1; g_cnt[grp] = 0u; }  // self-reset for replay
        else            { sLast = 0; }
    }
    __syncthreads();
    if (!sLast) return;

    // ---------------- MLP tail: 4 blks, 256 threads fully active ----------
    const int o   = (grp >> 3) & 7;             // ((grp*4)/32)%8
    const int sub = tid >> 6;                   // blk within group (0..3)
    const int n   = tid & 63;                   // output/hidden index
    const int blk = grp * 4 + sub;

    // pooled values for 4 blks (bypass L1 for cross-CTA visibility)
    {
        float2 p = __ldcg(&g_pool[blk * C_DIM + n]);
        spm[sub][n] = p.x;
        spx[sub][n] = p.y;
    }

    // stage w1 (coalesced float4 -> padded rows)
    const float4* w1g4 = reinterpret_cast<const float4*>(w1 + (size_t)o * C_DIM * C_DIM);
    #pragma unroll
    for (int i = 0; i < 4; ++i) {
        int idx = tid + i * 256;                // 0..1023 float4s
        ws4[(idx >> 4) * WPAD4 + (idx & 15)] = __ldg(w1g4 + idx);
    }
    __syncthreads();

    // FC1 + relu
    {
        const float4* wr = ws4 + n * WPAD4;
        const float4* p4 = reinterpret_cast<const float4*>(spm[sub]);
        const float4* q4 = reinterpret_cast<const float4*>(spx[sub]);
        float am = 0.0f, ax = 0.0f;
        #pragma unroll
        for (int c4 = 0; c4 < 16; ++c4) {
            float4 w = wr[c4];
            float4 p = p4[c4];
            float4 q = q4[c4];
            am = fmaf(w.x, p.x, am); am = fmaf(w.y, p.y, am);
            am = fmaf(w.z, p.z, am); am = fmaf(w.w, p.w, am);
            ax = fmaf(w.x, q.x, ax); ax = fmaf(w.y, q.y, ax);
            ax = fmaf(w.z, q.z, ax); ax = fmaf(w.w, q.w, ax);
        }
        shs[sub][n] = fmaxf(am, 0.0f) + fmaxf(ax, 0.0f);
    }
    __syncthreads();                            // FC1 done reading ws

    // stage w2 into the SAME buffer
    const float4* w2g4 = reinterpret_cast<const float4*>(w2 + (size_t)o * C_DIM * C_DIM);
    #pragma unroll
    for (int i = 0; i < 4; ++i) {
        int idx = tid + i * 256;
        ws4[(idx >> 4) * WPAD4 + (idx & 15)] = __ldg(w2g4 + idx);
    }
    __syncthreads();

    // FC2 + sigmoid (FC2 linear => single pass over summed hidden)
    {
        const float4* wr = ws4 + n * WPAD4;
        const float4* h4 = reinterpret_cast<const float4*>(shs[sub]);
        float a = 0.0f;
        #pragma unroll
        for (int c4 = 0; c4 < 16; ++c4) {
            float4 w = wr[c4];
            float4 h = h4[c4];
            a = fmaf(w.x, h.x, a); a = fmaf(w.y, h.y, a);
            a = fmaf(w.z, h.z, a); a = fmaf(w.w, h.w, a);
        }
        out[(size_t)blk * C_DIM + n] = 1.0f / (1.0f + __expf(-a));
    }
}

extern "C" void kernel_launch(void* const* d_in, const int* in_sizes, int n_in,
                              void* d_out, int out_size)
{
    const float* x  = (const float*)d_in[0];
    const float* w1 = (const float*)d_in[1];
    const float* w2 = (const float*)d_in[2];
    float* out = (float*)d_out;

    fused_kernel<<<NBLK * 8, 256>>>(x, w1, w2, out);
}